// round 16
// baseline (speedup 1.0000x reference)
#include <cuda_runtime.h>
#include <math.h>

#define NPTS 8192
#define DDIM 64
#define NN ((size_t)NPTS * (size_t)NPTS)
#define NITER 50
#define K1 33554432LL   /* 1-based rank of lower middle element (n*n/2) */

#define PBLOCKS 128
#define PTHREADS 1024

// fp8(e4m3, sign=0) -> f32 * 2^-120 via integer shift (subnormals exact)
#define F8(w,k) __uint_as_float((((w) >> (8*(k))) & 0x7Fu) << 20)

// ---- scratch (no cudaMalloc allowed) ----
__device__ float g_M[67108864];          // 256 MB cost matrix (unnormalized)
__device__ unsigned char g_K8[67108864]; // 64 MB e4m3 kernel
__device__ float g_v[NPTS];              // v * 2^120 (built post-loop for k_loss)
__device__ float g_col[2][NPTS];         // ping-pong K^T u accumulators
__device__ float g_row[2][NPTS];         // ping-pong K v accumulators
__device__ float g_x2[NPTS], g_y2[NPTS];
__device__ unsigned int g_hist0[2048], g_hist1[2048], g_hist2[1024];
__device__ unsigned int g_prefix;
__device__ long long g_k;
__device__ unsigned long long g_cntLE;
__device__ unsigned int g_minGT;
__device__ unsigned int g_minAll;
__device__ volatile unsigned int g_barCount;
__device__ volatile unsigned int g_barGen;
__device__ float g_invMedReg;   // 10/med
__device__ float g_expS;        // ln(400) + Mmin*10/med
__device__ float g_lossScale;   // 1/med
__device__ double g_loss;

// ---------------- init ----------------
__global__ void k_init() {
    int idx = blockIdx.x * blockDim.x + threadIdx.x;
    if (idx < NPTS) {
        g_col[0][idx] = 0.0f;
        g_col[1][idx] = 0.0f;
        g_row[0][idx] = 0.0f;
        g_row[1][idx] = 1.0f;   // => u0 = mu = 1/N at A(0)
    }
    if (idx < 2048) { g_hist0[idx] = 0u; g_hist1[idx] = 0u; }
    if (idx < 1024) g_hist2[idx] = 0u;
    if (idx == 0) {
        g_loss = 0.0;
        g_prefix = 0u;
        g_k = K1;
        g_cntLE = 0ULL;
        g_minGT = 0xFFFFFFFFu;
        g_minAll = 0xFFFFFFFFu;
        g_barCount = 0u;
        g_barGen = 0u;
    }
}

// ---------------- row norms (warp per row) ----------------
__global__ void k_norms(const float* __restrict__ X, const float* __restrict__ Y) {
    int gw = (blockIdx.x * blockDim.x + threadIdx.x) >> 5;
    int lane = threadIdx.x & 31;
    if (gw >= 2 * NPTS) return;
    const float* src = (gw < NPTS) ? X : Y;
    int row = (gw < NPTS) ? gw : gw - NPTS;
    float2 p = ((const float2*)(src + (size_t)row * DDIM))[lane];
    float s = p.x * p.x + p.y * p.y;
    #pragma unroll
    for (int o = 16; o; o >>= 1) s += __shfl_xor_sync(0xFFFFFFFFu, s, o);
    if (lane == 0) { if (gw < NPTS) g_x2[row] = s; else g_y2[row] = s; }
}

// ---------------- M = sq-cdist GEMM + fused level-0 histogram + global min ----------------
__global__ void k_gemm(const float* __restrict__ X, const float* __restrict__ Y) {
    __shared__ float Xs[64][65];
    __shared__ float Ys[64][65];
    __shared__ unsigned int sh[2048];
    int tx = threadIdx.x, ty = threadIdx.y;
    int tid = ty * 16 + tx;
    int lane = tid & 31;
    int i0 = blockIdx.y * 64, j0 = blockIdx.x * 64;

    for (int t = tid; t < 2048; t += 256) sh[t] = 0u;
    for (int t = tid; t < 4096; t += 256) {
        int r = t >> 6, c = t & 63;
        Xs[r][c] = X[(size_t)(i0 + r) * DDIM + c];
        Ys[r][c] = Y[(size_t)(j0 + r) * DDIM + c];
    }
    __syncthreads();

    float acc[4][4] = {};
    #pragma unroll 16
    for (int k = 0; k < 64; k++) {
        float a[4], b[4];
        #pragma unroll
        for (int r = 0; r < 4; r++) a[r] = Xs[ty * 4 + r][k];
        #pragma unroll
        for (int c = 0; c < 4; c++) b[c] = Ys[tx * 4 + c][k];
        #pragma unroll
        for (int r = 0; r < 4; r++)
            #pragma unroll
            for (int c = 0; c < 4; c++) acc[r][c] += a[r] * b[c];
    }

    float lmin = 3.4e38f;
    #pragma unroll
    for (int r = 0; r < 4; r++) {
        int i = i0 + ty * 4 + r;
        float xi = g_x2[i];
        float4 outv;
        float* o = &outv.x;
        #pragma unroll
        for (int c = 0; c < 4; c++) {
            int j = j0 + tx * 4 + c;
            float m = fmaxf(xi + g_y2[j] - 2.0f * acc[r][c], 0.0f);
            o[c] = m;
            lmin = fminf(lmin, m);
            unsigned bin = __float_as_uint(m) >> 21;
            unsigned mask = __match_any_sync(0xFFFFFFFFu, bin);
            if (lane == (__ffs(mask) - 1)) atomicAdd(&sh[bin], (unsigned)__popc(mask));
        }
        *(float4*)&g_M[(size_t)i * NPTS + j0 + tx * 4] = outv;
    }
    unsigned lm = __float_as_uint(lmin);
    #pragma unroll
    for (int o = 16; o; o >>= 1) lm = min(lm, __shfl_xor_sync(0xFFFFFFFFu, lm, o));
    if (lane == 0) atomicMin(&g_minAll, lm);
    __syncthreads();
    for (int t = tid; t < 2048; t += 256)
        if (sh[t]) atomicAdd(&g_hist0[t], sh[t]);
}

// ---------------- radix-select scan (block-cooperative, compile-time level) ----------------
template <int LEVEL>
__global__ void k_scan() {
    constexpr int BITS = (LEVEL < 2) ? 11 : 10;
    constexpr int PER = (1 << BITS) >> 8;   // 8 or 4
    __shared__ unsigned int sums[256];
    __shared__ int sh_b;
    __shared__ long long sh_k;
    int t = threadIdx.x;
    const unsigned int* hist = (LEVEL == 0) ? g_hist0 : (LEVEL == 1) ? g_hist1 : g_hist2;
    unsigned int vals[PER];
    unsigned int local = 0;
    #pragma unroll
    for (int i = 0; i < PER; i++) { vals[i] = hist[t * PER + i]; local += vals[i]; }
    sums[t] = local;
    __syncthreads();
    if (t == 0) {
        long long k = g_k, c = 0;
        int b = 0;
        for (; b < 255; b++) {
            long long h = (long long)sums[b];
            if (c + h >= k) break;
            c += h;
        }
        sh_b = b;
        sh_k = k - c;
    }
    __syncthreads();
    if (t == sh_b) {
        long long k2 = sh_k, c = 0;
        int sel = PER - 1;
        #pragma unroll
        for (int i = 0; i < PER - 1; i++) {
            long long h = (long long)vals[i];
            if (sel == PER - 1) {
                if (c + h >= k2) sel = i;
                else c += h;
            }
        }
        g_k = k2 - c;
        g_prefix = (g_prefix << BITS) | (unsigned)(t * PER + sel);
    }
}

// ---------------- filtered histogram passes (levels 1, 2) ----------------
template <int LEVEL>
__global__ void k_hist() {
    constexpr int NB = (LEVEL == 1) ? 2048 : 1024;
    __shared__ unsigned int sh[NB];
    int tid = threadIdx.x;
    for (int t = tid; t < NB; t += blockDim.x) sh[t] = 0u;
    __syncthreads();
    unsigned pref = g_prefix;
    size_t stride = (size_t)gridDim.x * blockDim.x;
    for (size_t idx = (size_t)blockIdx.x * blockDim.x + tid; idx < NN; idx += stride) {
        unsigned bv = __float_as_uint(g_M[idx]);
        if (LEVEL == 1) {
            if ((bv >> 21) == pref) atomicAdd(&sh[(bv >> 10) & 2047u], 1u);
        } else {
            if ((bv >> 10) == pref) atomicAdd(&sh[bv & 1023u], 1u);
        }
    }
    __syncthreads();
    unsigned int* dst = (LEVEL == 1) ? g_hist1 : g_hist2;
    for (int t = tid; t < NB; t += blockDim.x)
        if (sh[t]) atomicAdd(&dst[t], sh[t]);
}

// ---------------- count <= v1, min of elements > v1 ----------------
__global__ void k_cntmin() {
    unsigned v1 = g_prefix;
    unsigned long long cnt = 0ULL;
    unsigned mn = 0xFFFFFFFFu;
    size_t stride = (size_t)gridDim.x * blockDim.x;
    for (size_t idx = (size_t)blockIdx.x * blockDim.x + threadIdx.x; idx < NN; idx += stride) {
        unsigned bv = __float_as_uint(g_M[idx]);
        if (bv <= v1) cnt++;
        else mn = min(mn, bv);
    }
    #pragma unroll
    for (int o = 16; o; o >>= 1) {
        cnt += __shfl_xor_sync(0xFFFFFFFFu, cnt, o);
        mn = min(mn, __shfl_xor_sync(0xFFFFFFFFu, mn, o));
    }
    if ((threadIdx.x & 31) == 0) {
        atomicAdd(&g_cntLE, cnt);
        atomicMin(&g_minGT, mn);
    }
}

// ---------------- median finalize ----------------
__global__ void k_med() {
    float v1 = __uint_as_float(g_prefix);
    float v2 = (g_cntLE >= (unsigned long long)(K1 + 1)) ? v1 : __uint_as_float(g_minGT);
    float med = 0.5f * (v1 + v2);
    float inv;
    if (med > 0.0f) {
        inv = 10.0f / med;
        g_lossScale = 1.0f / med;
    } else {
        inv = 10.0f;
        g_lossScale = 1.0f;
    }
    g_invMedReg = inv;
    g_expS = 5.9915f + __uint_as_float(g_minAll) * inv;  // max K8 entry ~400
}

// ---------------- K8 = e4m3( exp(s - M*10/med) ) ----------------
__global__ void k_gibbs() {
    float inv = g_invMedReg;
    float s = g_expS;
    size_t stride = (size_t)gridDim.x * blockDim.x;
    const float4* Mi = (const float4*)g_M;
    uint4* Ko = (uint4*)g_K8;
    for (size_t q = (size_t)blockIdx.x * blockDim.x + threadIdx.x; q < NN / 16; q += stride) {
        unsigned wds[4];
        #pragma unroll
        for (int h = 0; h < 4; h++) {
            float4 m = Mi[4 * q + h];
            float e0 = __expf(s - m.x * inv);
            float e1 = __expf(s - m.y * inv);
            float e2 = __expf(s - m.z * inv);
            float e3 = __expf(s - m.w * inv);
            unsigned short lo, hi;
            asm("cvt.rn.satfinite.e4m3x2.f32 %0, %1, %2;" : "=h"(lo) : "f"(e1), "f"(e0));
            asm("cvt.rn.satfinite.e4m3x2.f32 %0, %1, %2;" : "=h"(hi) : "f"(e3), "f"(e2));
            wds[h] = (unsigned)lo | ((unsigned)hi << 16);
        }
        Ko[q] = make_uint4(wds[0], wds[1], wds[2], wds[3]);
    }
}

// ---------------- persistent Sinkhorn loop: 2 phases, ping-pong buffers ----------------
__device__ __forceinline__ void grid_sync() {
    __syncthreads();
    if (threadIdx.x == 0) {
        __threadfence();
        unsigned gen = g_barGen;
        if (atomicAdd((unsigned int*)&g_barCount, 1u) == PBLOCKS - 1) {
            g_barCount = 0u;
            __threadfence();
            g_barGen = gen + 1u;
        } else {
            while (g_barGen == gen) { __nanosleep(32); }
        }
        __threadfence();
    }
    __syncthreads();
}

__global__ void __launch_bounds__(PTHREADS, 1) k_sink() {
    int tid = threadIdx.x;
    int bid = blockIdx.x;
    int lane = tid & 31;
    int warp = tid >> 5;
    int r0 = bid * 64;
    __shared__ float us[64];      // u * 2^120 for this block's 64 rows
    __shared__ float sAcc[8192];  // cross-half column partials

    for (int it = 0; it < NITER; it++) {
        int p = it & 1;
        // ---- Phase A: col[p]_j += sum_i K8_ij * u_i,  u = mu/row[1-p]
        //      also zero row[p] (readers A(it-1) done; writers C(it) after sync)
        if (tid < 64) {
            us[tid] = (1.0f / NPTS) / __ldcg(&g_row[1 - p][r0 + tid]) * 0x1p120f;
            __stcg(&g_row[p][r0 + tid], 0.0f);
        }
        __syncthreads();
        {
            int c = tid & 511;              // uint4 column group (16 elems)
            int rbase = (tid >> 9) * 32;    // 0 or 32
            const uint4* Kb = (const uint4*)(g_K8 + (size_t)(r0 + rbase) * NPTS) + c;
            float acc[16];
            #pragma unroll
            for (int e = 0; e < 16; e++) acc[e] = 0.f;
            #pragma unroll 4
            for (int r = 0; r < 32; r++) {
                float uu = us[rbase + r];
                uint4 kv = Kb[(size_t)r * (NPTS / 16)];
                unsigned w0 = kv.x, w1 = kv.y, w2 = kv.z, w3 = kv.w;
                acc[0]  += F8(w0,0)*uu; acc[1]  += F8(w0,1)*uu; acc[2]  += F8(w0,2)*uu; acc[3]  += F8(w0,3)*uu;
                acc[4]  += F8(w1,0)*uu; acc[5]  += F8(w1,1)*uu; acc[6]  += F8(w1,2)*uu; acc[7]  += F8(w1,3)*uu;
                acc[8]  += F8(w2,0)*uu; acc[9]  += F8(w2,1)*uu; acc[10] += F8(w2,2)*uu; acc[11] += F8(w2,3)*uu;
                acc[12] += F8(w3,0)*uu; acc[13] += F8(w3,1)*uu; acc[14] += F8(w3,2)*uu; acc[15] += F8(w3,3)*uu;
            }
            if (tid >= 512) {
                #pragma unroll
                for (int e = 0; e < 16; e++) sAcc[e * 512 + c] = acc[e];
            }
            __syncthreads();
            if (tid < 512) {
                #pragma unroll
                for (int e = 0; e < 16; e++)
                    atomicAdd(&g_col[p][c * 16 + e], acc[e] + sAcc[e * 512 + c]);
            }
        }
        grid_sync();

        // ---- Phase C: row[p]_i += sum_j K8_ij * v_j,  v = nu/col[p] (on the fly)
        //      also zero col[1-p] (readers C(it-1) done; writers A(it+1) after sync)
        if (tid < 64) __stcg(&g_col[1 - p][r0 + tid], 0.0f);
        {
            int gw = bid * 32 + warp;       // 0..4095
            int s = gw & 15;                // column strip (512 cols)
            int row0 = (gw >> 4) * 32;      // 32-row block
            float vr[16];
            const float4* C4 = (const float4*)g_col[p] + (s * 128 + lane * 4);
            #pragma unroll
            for (int h = 0; h < 4; h++) {
                float4 t = __ldcg(&C4[h]);
                vr[h*4+0] = (0x1p120f / NPTS) * __frcp_rn(t.x);
                vr[h*4+1] = (0x1p120f / NPTS) * __frcp_rn(t.y);
                vr[h*4+2] = (0x1p120f / NPTS) * __frcp_rn(t.z);
                vr[h*4+3] = (0x1p120f / NPTS) * __frcp_rn(t.w);
            }
            const uint4* Kb = (const uint4*)g_K8 + (size_t)row0 * (NPTS / 16) + s * 32 + lane;
            #pragma unroll 4
            for (int r = 0; r < 32; r++) {
                uint4 kv = Kb[(size_t)r * (NPTS / 16)];
                unsigned w0 = kv.x, w1 = kv.y, w2 = kv.z, w3 = kv.w;
                float sm;
                sm  = F8(w0,0)*vr[0]  + F8(w0,1)*vr[1]  + F8(w0,2)*vr[2]  + F8(w0,3)*vr[3];
                sm += F8(w1,0)*vr[4]  + F8(w1,1)*vr[5]  + F8(w1,2)*vr[6]  + F8(w1,3)*vr[7];
                sm += F8(w2,0)*vr[8]  + F8(w2,1)*vr[9]  + F8(w2,2)*vr[10] + F8(w2,3)*vr[11];
                sm += F8(w3,0)*vr[12] + F8(w3,1)*vr[13] + F8(w3,2)*vr[14] + F8(w3,3)*vr[15];
                #pragma unroll
                for (int o = 16; o; o >>= 1) sm += __shfl_xor_sync(0xFFFFFFFFu, sm, o);
                if (lane == 0) atomicAdd(&g_row[p][row0 + r], sm);
            }
        }
        grid_sync();
    }
}

// ---------------- v' = (nu/col[1]) * 2^120  (final, for loss) ----------------
__global__ void k_vfin() {
    int j = blockIdx.x * blockDim.x + threadIdx.x;
    if (j < NPTS) g_v[j] = (1.0f / NPTS) / g_col[1][j] * 0x1p120f;
}

// ---------------- loss = sum u_i K8_ij v_j M_ij  (u = mu/row[1]) ----------------
__global__ void k_loss() {
    double acc = 0.0;
    size_t stride = (size_t)gridDim.x * blockDim.x;
    const uint4* Kp = (const uint4*)g_K8;
    const float4* Mp = (const float4*)g_M;
    const float4* Vp = (const float4*)g_v;
    for (size_t q = (size_t)blockIdx.x * blockDim.x + threadIdx.x; q < NN / 16; q += stride) {
        size_t i = q >> 9;             // q*16 / 8192
        int j16 = (int)(q & 511);
        uint4 kq = Kp[q];
        unsigned w0 = kq.x, w1 = kq.y, w2 = kq.z, w3 = kq.w;
        float ui = (1.0f / NPTS) / g_row[1][i];
        float4 m0 = Mp[4*q+0], m1 = Mp[4*q+1], m2 = Mp[4*q+2], m3 = Mp[4*q+3];
        float4 v0 = Vp[4*j16+0], v1 = Vp[4*j16+1], v2 = Vp[4*j16+2], v3 = Vp[4*j16+3];
        float t;
        t  = F8(w0,0)*v0.x*m0.x + F8(w0,1)*v0.y*m0.y + F8(w0,2)*v0.z*m0.z + F8(w0,3)*v0.w*m0.w;
        t += F8(w1,0)*v1.x*m1.x + F8(w1,1)*v1.y*m1.y + F8(w1,2)*v1.z*m1.z + F8(w1,3)*v1.w*m1.w;
        t += F8(w2,0)*v2.x*m2.x + F8(w2,1)*v2.y*m2.y + F8(w2,2)*v2.z*m2.z + F8(w2,3)*v2.w*m2.w;
        t += F8(w3,0)*v3.x*m3.x + F8(w3,1)*v3.y*m3.y + F8(w3,2)*v3.z*m3.z + F8(w3,3)*v3.w*m3.w;
        acc += (double)ui * (double)t;
    }
    #pragma unroll
    for (int o = 16; o; o >>= 1) acc += __shfl_xor_sync(0xFFFFFFFFu, acc, o);
    __shared__ double sh[8];
    int warp = threadIdx.x >> 5, lane = threadIdx.x & 31;
    if (lane == 0) sh[warp] = acc;
    __syncthreads();
    if (threadIdx.x == 0) {
        double s = 0.0;
        #pragma unroll
        for (int w = 0; w < 8; w++) s += sh[w];
        atomicAdd(&g_loss, s);
    }
}

__global__ void k_out(float* out) {
    out[0] = (float)(g_loss * (double)g_lossScale);
}

extern "C" void kernel_launch(void* const* d_in, const int* in_sizes, int n_in,
                              void* d_out, int out_size) {
    const float* X = (const float*)d_in[0];
    const float* Y = (const float*)d_in[1];

    k_init<<<32, 256>>>();
    k_norms<<<2048, 256>>>(X, Y);
    k_gemm<<<dim3(128, 128), dim3(16, 16)>>>(X, Y);
    k_scan<0><<<1, 256>>>();
    k_hist<1><<<2048, 256>>>();
    k_scan<1><<<1, 256>>>();
    k_hist<2><<<2048, 256>>>();
    k_scan<2><<<1, 256>>>();
    k_cntmin<<<2048, 256>>>();
    k_med<<<1, 1>>>();
    k_gibbs<<<2048, 256>>>();

    k_sink<<<PBLOCKS, PTHREADS>>>();

    k_vfin<<<32, 256>>>();
    k_loss<<<1024, 256>>>();
    k_out<<<1, 1>>>((float*)d_out);
}

// round 17
// speedup vs baseline: 1.0492x; 1.0492x over previous
#include <cuda_runtime.h>
#include <math.h>

#define NPTS 8192
#define DDIM 64
#define NN ((size_t)NPTS * (size_t)NPTS)
#define NITER 50
#define K1 33554432LL   /* 1-based rank of lower middle element (n*n/2) */

#define PBLOCKS 148
#define PTHREADS 1024
#define AROWS 56            /* Phase A rows per block (148*56 >= 8192) */
#define CWPS 296            /* Phase C warps per strip (16*296 = 4736) */
#define CROWS 28            /* Phase C rows per warp (296*28 >= 8192) */

// fp8(e4m3, sign=0) -> f32 * 2^-120 via integer shift (subnormals exact)
#define F8(w,k) __uint_as_float((((w) >> (8*(k))) & 0x7Fu) << 20)

// ---- scratch (no cudaMalloc allowed) ----
__device__ float g_M[67108864];          // 256 MB cost matrix (unnormalized)
__device__ unsigned char g_K8[67108864]; // 64 MB e4m3 kernel
__device__ float g_v[NPTS];              // v * 2^120
__device__ float g_tmp[NPTS], g_tmp2[NPTS];
__device__ float g_x2[NPTS], g_y2[NPTS];
__device__ unsigned int g_hist0[2048], g_hist1[2048], g_hist2[1024];
__device__ unsigned int g_prefix;
__device__ long long g_k;
__device__ unsigned long long g_cntLE;
__device__ unsigned int g_minGT;
__device__ unsigned int g_minAll;
__device__ volatile unsigned int g_barCount;
__device__ volatile unsigned int g_barGen;
__device__ float g_invMedReg;   // 10/med
__device__ float g_expS;        // ln(400) + Mmin*10/med
__device__ float g_lossScale;   // 1/med
__device__ double g_loss;

// ---------------- init ----------------
__global__ void k_init() {
    int idx = blockIdx.x * blockDim.x + threadIdx.x;
    if (idx < NPTS) { g_tmp[idx] = 0.0f; g_tmp2[idx] = 1.0f; }  // tmp2=1 => u0 = 1/N
    if (idx < 2048) { g_hist0[idx] = 0u; g_hist1[idx] = 0u; }
    if (idx < 1024) g_hist2[idx] = 0u;
    if (idx == 0) {
        g_loss = 0.0;
        g_prefix = 0u;
        g_k = K1;
        g_cntLE = 0ULL;
        g_minGT = 0xFFFFFFFFu;
        g_minAll = 0xFFFFFFFFu;
        g_barCount = 0u;
        g_barGen = 0u;
    }
}

// ---------------- row norms (warp per row) ----------------
__global__ void k_norms(const float* __restrict__ X, const float* __restrict__ Y) {
    int gw = (blockIdx.x * blockDim.x + threadIdx.x) >> 5;
    int lane = threadIdx.x & 31;
    if (gw >= 2 * NPTS) return;
    const float* src = (gw < NPTS) ? X : Y;
    int row = (gw < NPTS) ? gw : gw - NPTS;
    float2 p = ((const float2*)(src + (size_t)row * DDIM))[lane];
    float s = p.x * p.x + p.y * p.y;
    #pragma unroll
    for (int o = 16; o; o >>= 1) s += __shfl_xor_sync(0xFFFFFFFFu, s, o);
    if (lane == 0) { if (gw < NPTS) g_x2[row] = s; else g_y2[row] = s; }
}

// ---------------- M = sq-cdist GEMM + fused level-0 histogram + global min ----------------
__global__ void k_gemm(const float* __restrict__ X, const float* __restrict__ Y) {
    __shared__ float Xs[64][65];
    __shared__ float Ys[64][65];
    __shared__ unsigned int sh[2048];
    int tx = threadIdx.x, ty = threadIdx.y;
    int tid = ty * 16 + tx;
    int lane = tid & 31;
    int i0 = blockIdx.y * 64, j0 = blockIdx.x * 64;

    for (int t = tid; t < 2048; t += 256) sh[t] = 0u;
    for (int t = tid; t < 4096; t += 256) {
        int r = t >> 6, c = t & 63;
        Xs[r][c] = X[(size_t)(i0 + r) * DDIM + c];
        Ys[r][c] = Y[(size_t)(j0 + r) * DDIM + c];
    }
    __syncthreads();

    float acc[4][4] = {};
    #pragma unroll 16
    for (int k = 0; k < 64; k++) {
        float a[4], b[4];
        #pragma unroll
        for (int r = 0; r < 4; r++) a[r] = Xs[ty * 4 + r][k];
        #pragma unroll
        for (int c = 0; c < 4; c++) b[c] = Ys[tx * 4 + c][k];
        #pragma unroll
        for (int r = 0; r < 4; r++)
            #pragma unroll
            for (int c = 0; c < 4; c++) acc[r][c] += a[r] * b[c];
    }

    float lmin = 3.4e38f;
    #pragma unroll
    for (int r = 0; r < 4; r++) {
        int i = i0 + ty * 4 + r;
        float xi = g_x2[i];
        float4 outv;
        float* o = &outv.x;
        #pragma unroll
        for (int c = 0; c < 4; c++) {
            int j = j0 + tx * 4 + c;
            float m = fmaxf(xi + g_y2[j] - 2.0f * acc[r][c], 0.0f);
            o[c] = m;
            lmin = fminf(lmin, m);
            unsigned bin = __float_as_uint(m) >> 21;
            unsigned mask = __match_any_sync(0xFFFFFFFFu, bin);
            if (lane == (__ffs(mask) - 1)) atomicAdd(&sh[bin], (unsigned)__popc(mask));
        }
        *(float4*)&g_M[(size_t)i * NPTS + j0 + tx * 4] = outv;
    }
    unsigned lm = __float_as_uint(lmin);
    #pragma unroll
    for (int o = 16; o; o >>= 1) lm = min(lm, __shfl_xor_sync(0xFFFFFFFFu, lm, o));
    if (lane == 0) atomicMin(&g_minAll, lm);
    __syncthreads();
    for (int t = tid; t < 2048; t += 256)
        if (sh[t]) atomicAdd(&g_hist0[t], sh[t]);
}

// ---------------- radix-select scan (block-cooperative, compile-time level) ----------------
template <int LEVEL>
__global__ void k_scan() {
    constexpr int BITS = (LEVEL < 2) ? 11 : 10;
    constexpr int PER = (1 << BITS) >> 8;   // 8 or 4
    __shared__ unsigned int sums[256];
    __shared__ int sh_b;
    __shared__ long long sh_k;
    int t = threadIdx.x;
    const unsigned int* hist = (LEVEL == 0) ? g_hist0 : (LEVEL == 1) ? g_hist1 : g_hist2;
    unsigned int vals[PER];
    unsigned int local = 0;
    #pragma unroll
    for (int i = 0; i < PER; i++) { vals[i] = hist[t * PER + i]; local += vals[i]; }
    sums[t] = local;
    __syncthreads();
    if (t == 0) {
        long long k = g_k, c = 0;
        int b = 0;
        for (; b < 255; b++) {
            long long h = (long long)sums[b];
            if (c + h >= k) break;
            c += h;
        }
        sh_b = b;
        sh_k = k - c;
    }
    __syncthreads();
    if (t == sh_b) {
        long long k2 = sh_k, c = 0;
        int sel = PER - 1;
        #pragma unroll
        for (int i = 0; i < PER - 1; i++) {
            long long h = (long long)vals[i];
            if (sel == PER - 1) {
                if (c + h >= k2) sel = i;
                else c += h;
            }
        }
        g_k = k2 - c;
        g_prefix = (g_prefix << BITS) | (unsigned)(t * PER + sel);
    }
}

// ---------------- filtered histogram passes (levels 1, 2) ----------------
template <int LEVEL>
__global__ void k_hist() {
    constexpr int NB = (LEVEL == 1) ? 2048 : 1024;
    __shared__ unsigned int sh[NB];
    int tid = threadIdx.x;
    for (int t = tid; t < NB; t += blockDim.x) sh[t] = 0u;
    __syncthreads();
    unsigned pref = g_prefix;
    size_t stride = (size_t)gridDim.x * blockDim.x;
    for (size_t idx = (size_t)blockIdx.x * blockDim.x + tid; idx < NN; idx += stride) {
        unsigned bv = __float_as_uint(g_M[idx]);
        if (LEVEL == 1) {
            if ((bv >> 21) == pref) atomicAdd(&sh[(bv >> 10) & 2047u], 1u);
        } else {
            if ((bv >> 10) == pref) atomicAdd(&sh[bv & 1023u], 1u);
        }
    }
    __syncthreads();
    unsigned int* dst = (LEVEL == 1) ? g_hist1 : g_hist2;
    for (int t = tid; t < NB; t += blockDim.x)
        if (sh[t]) atomicAdd(&dst[t], sh[t]);
}

// ---------------- count <= v1, min of elements > v1 ----------------
__global__ void k_cntmin() {
    unsigned v1 = g_prefix;
    unsigned long long cnt = 0ULL;
    unsigned mn = 0xFFFFFFFFu;
    size_t stride = (size_t)gridDim.x * blockDim.x;
    for (size_t idx = (size_t)blockIdx.x * blockDim.x + threadIdx.x; idx < NN; idx += stride) {
        unsigned bv = __float_as_uint(g_M[idx]);
        if (bv <= v1) cnt++;
        else mn = min(mn, bv);
    }
    #pragma unroll
    for (int o = 16; o; o >>= 1) {
        cnt += __shfl_xor_sync(0xFFFFFFFFu, cnt, o);
        mn = min(mn, __shfl_xor_sync(0xFFFFFFFFu, mn, o));
    }
    if ((threadIdx.x & 31) == 0) {
        atomicAdd(&g_cntLE, cnt);
        atomicMin(&g_minGT, mn);
    }
}

// ---------------- median finalize ----------------
__global__ void k_med() {
    float v1 = __uint_as_float(g_prefix);
    float v2 = (g_cntLE >= (unsigned long long)(K1 + 1)) ? v1 : __uint_as_float(g_minGT);
    float med = 0.5f * (v1 + v2);
    float inv;
    if (med > 0.0f) {
        inv = 10.0f / med;
        g_lossScale = 1.0f / med;
    } else {
        inv = 10.0f;
        g_lossScale = 1.0f;
    }
    g_invMedReg = inv;
    g_expS = 5.9915f + __uint_as_float(g_minAll) * inv;  // max K8 entry ~400
}

// ---------------- K8 = e4m3( exp(s - M*10/med) ) ----------------
__global__ void k_gibbs() {
    float inv = g_invMedReg;
    float s = g_expS;
    size_t stride = (size_t)gridDim.x * blockDim.x;
    const float4* Mi = (const float4*)g_M;
    uint4* Ko = (uint4*)g_K8;
    for (size_t q = (size_t)blockIdx.x * blockDim.x + threadIdx.x; q < NN / 16; q += stride) {
        unsigned wds[4];
        #pragma unroll
        for (int h = 0; h < 4; h++) {
            float4 m = Mi[4 * q + h];
            float e0 = __expf(s - m.x * inv);
            float e1 = __expf(s - m.y * inv);
            float e2 = __expf(s - m.z * inv);
            float e3 = __expf(s - m.w * inv);
            unsigned short lo, hi;
            asm("cvt.rn.satfinite.e4m3x2.f32 %0, %1, %2;" : "=h"(lo) : "f"(e1), "f"(e0));
            asm("cvt.rn.satfinite.e4m3x2.f32 %0, %1, %2;" : "=h"(hi) : "f"(e3), "f"(e2));
            wds[h] = (unsigned)lo | ((unsigned)hi << 16);
        }
        Ko[q] = make_uint4(wds[0], wds[1], wds[2], wds[3]);
    }
}

// ---------------- persistent Sinkhorn loop (148 blocks = all SMs) ----------------
__device__ __forceinline__ void grid_sync() {
    __syncthreads();
    if (threadIdx.x == 0) {
        __threadfence();
        unsigned gen = g_barGen;
        if (atomicAdd((unsigned int*)&g_barCount, 1u) == PBLOCKS - 1) {
            g_barCount = 0u;
            __threadfence();
            g_barGen = gen + 1u;
        } else {
            while (g_barGen == gen) { __nanosleep(32); }
        }
        __threadfence();
    }
    __syncthreads();
}

__global__ void __launch_bounds__(PTHREADS, 1) k_sink() {
    int tid = threadIdx.x;
    int bid = blockIdx.x;
    int lane = tid & 31;
    int warp = tid >> 5;
    __shared__ float us[AROWS];   // u * 2^120 for this block's rows
    __shared__ float sAcc[8192];  // cross-half column partials

    // Phase A partition: rows [r0, r0+rcnt), rcnt even
    int r0 = bid * AROWS;
    int rcnt = NPTS - r0;
    if (rcnt > AROWS) rcnt = AROWS;
    if (rcnt < 0) rcnt = 0;
    int rh = rcnt >> 1;

    // Phase C partition: strip s (512 cols), rows [crs, cre)
    int gw = bid * 32 + warp;            // 0..4735 = 16 * 296
    int cs = gw / CWPS;                  // strip 0..15
    int cw = gw - cs * CWPS;             // 0..295
    int crs = cw * CROWS;
    int cre = crs + CROWS;
    if (cre > NPTS) cre = NPTS;

    for (int it = 0; it < NITER; it++) {
        // ---- Phase A: tmp_j += sum_i K8_ij * u_i ; u_i = mu / tmp2_i on the fly
        if (rcnt > 0) {
            if (tid < rcnt) us[tid] = (1.0f / NPTS) / __ldcg(&g_tmp2[r0 + tid]) * 0x1p120f;
            __syncthreads();
            int c = tid & 511;              // uint4 column group (16 elems)
            int rbase = (tid >> 9) * rh;    // 0 or rh
            const uint4* Kb = (const uint4*)(g_K8 + (size_t)(r0 + rbase) * NPTS) + c;
            float acc[16];
            #pragma unroll
            for (int e = 0; e < 16; e++) acc[e] = 0.f;
            #pragma unroll 4
            for (int r = 0; r < rh; r++) {
                float uu = us[rbase + r];
                uint4 kv = Kb[(size_t)r * (NPTS / 16)];
                unsigned w0 = kv.x, w1 = kv.y, w2 = kv.z, w3 = kv.w;
                acc[0]  += F8(w0,0)*uu; acc[1]  += F8(w0,1)*uu; acc[2]  += F8(w0,2)*uu; acc[3]  += F8(w0,3)*uu;
                acc[4]  += F8(w1,0)*uu; acc[5]  += F8(w1,1)*uu; acc[6]  += F8(w1,2)*uu; acc[7]  += F8(w1,3)*uu;
                acc[8]  += F8(w2,0)*uu; acc[9]  += F8(w2,1)*uu; acc[10] += F8(w2,2)*uu; acc[11] += F8(w2,3)*uu;
                acc[12] += F8(w3,0)*uu; acc[13] += F8(w3,1)*uu; acc[14] += F8(w3,2)*uu; acc[15] += F8(w3,3)*uu;
            }
            if (tid >= 512) {
                #pragma unroll
                for (int e = 0; e < 16; e++) sAcc[e * 512 + c] = acc[e];
            }
            __syncthreads();
            if (tid < 512) {
                #pragma unroll
                for (int e = 0; e < 16; e++)
                    atomicAdd(&g_tmp[c * 16 + e], acc[e] + sAcc[e * 512 + c]);
            }
        }
        grid_sync();

        // ---- Phase B: v' = (nu/tmp)*2^120 ; tmp = 0 ; tmp2 = 0
        {
            int g = bid * PTHREADS + tid;
            if (g < NPTS) {
                g_v[g] = (1.0f / NPTS) / __ldcg(&g_tmp[g]) * 0x1p120f;
                g_tmp[g] = 0.0f;
                g_tmp2[g] = 0.0f;
            }
        }
        grid_sync();

        // ---- Phase C: tmp2_i += sum_j K8_ij v'_j (strip warps, v in regs)
        if (crs < cre) {
            float vr[16];
            const float4* V4 = (const float4*)g_v + (cs * 128 + lane * 4);
            #pragma unroll
            for (int h = 0; h < 4; h++) {
                float4 t = __ldcg(&V4[h]);
                vr[h*4] = t.x; vr[h*4+1] = t.y; vr[h*4+2] = t.z; vr[h*4+3] = t.w;
            }
            const uint4* Kb = (const uint4*)g_K8 + cs * 32 + lane;
            #pragma unroll 4
            for (int r = crs; r < cre; r++) {
                uint4 kv = Kb[(size_t)r * (NPTS / 16)];
                unsigned w0 = kv.x, w1 = kv.y, w2 = kv.z, w3 = kv.w;
                float sm;
                sm  = F8(w0,0)*vr[0]  + F8(w0,1)*vr[1]  + F8(w0,2)*vr[2]  + F8(w0,3)*vr[3];
                sm += F8(w1,0)*vr[4]  + F8(w1,1)*vr[5]  + F8(w1,2)*vr[6]  + F8(w1,3)*vr[7];
                sm += F8(w2,0)*vr[8]  + F8(w2,1)*vr[9]  + F8(w2,2)*vr[10] + F8(w2,3)*vr[11];
                sm += F8(w3,0)*vr[12] + F8(w3,1)*vr[13] + F8(w3,2)*vr[14] + F8(w3,3)*vr[15];
                #pragma unroll
                for (int o = 16; o; o >>= 1) sm += __shfl_xor_sync(0xFFFFFFFFu, sm, o);
                if (lane == 0) atomicAdd(&g_tmp2[r], sm);
            }
        }
        grid_sync();
    }
}

// ---------------- loss = sum u_i K8_ij v_j M_ij  (u = mu/tmp2) ----------------
__global__ void k_loss() {
    double acc = 0.0;
    size_t stride = (size_t)gridDim.x * blockDim.x;
    const uint4* Kp = (const uint4*)g_K8;
    const float4* Mp = (const float4*)g_M;
    const float4* Vp = (const float4*)g_v;
    for (size_t q = (size_t)blockIdx.x * blockDim.x + threadIdx.x; q < NN / 16; q += stride) {
        size_t i = q >> 9;             // q*16 / 8192
        int j16 = (int)(q & 511);
        uint4 kq = Kp[q];
        unsigned w0 = kq.x, w1 = kq.y, w2 = kq.z, w3 = kq.w;
        float ui = (1.0f / NPTS) / g_tmp2[i];
        float4 m0 = Mp[4*q+0], m1 = Mp[4*q+1], m2 = Mp[4*q+2], m3 = Mp[4*q+3];
        float4 v0 = Vp[4*j16+0], v1 = Vp[4*j16+1], v2 = Vp[4*j16+2], v3 = Vp[4*j16+3];
        float t;
        t  = F8(w0,0)*v0.x*m0.x + F8(w0,1)*v0.y*m0.y + F8(w0,2)*v0.z*m0.z + F8(w0,3)*v0.w*m0.w;
        t += F8(w1,0)*v1.x*m1.x + F8(w1,1)*v1.y*m1.y + F8(w1,2)*v1.z*m1.z + F8(w1,3)*v1.w*m1.w;
        t += F8(w2,0)*v2.x*m2.x + F8(w2,1)*v2.y*m2.y + F8(w2,2)*v2.z*m2.z + F8(w2,3)*v2.w*m2.w;
        t += F8(w3,0)*v3.x*m3.x + F8(w3,1)*v3.y*m3.y + F8(w3,2)*v3.z*m3.z + F8(w3,3)*v3.w*m3.w;
        acc += (double)ui * (double)t;
    }
    #pragma unroll
    for (int o = 16; o; o >>= 1) acc += __shfl_xor_sync(0xFFFFFFFFu, acc, o);
    __shared__ double sh[8];
    int warp = threadIdx.x >> 5, lane = threadIdx.x & 31;
    if (lane == 0) sh[warp] = acc;
    __syncthreads();
    if (threadIdx.x == 0) {
        double s = 0.0;
        #pragma unroll
        for (int w = 0; w < 8; w++) s += sh[w];
        atomicAdd(&g_loss, s);
    }
}

__global__ void k_out(float* out) {
    out[0] = (float)(g_loss * (double)g_lossScale);
}

extern "C" void kernel_launch(void* const* d_in, const int* in_sizes, int n_in,
                              void* d_out, int out_size) {
    const float* X = (const float*)d_in[0];
    const float* Y = (const float*)d_in[1];

    k_init<<<32, 256>>>();
    k_norms<<<2048, 256>>>(X, Y);
    k_gemm<<<dim3(128, 128), dim3(16, 16)>>>(X, Y);
    k_scan<0><<<1, 256>>>();
    k_hist<1><<<2048, 256>>>();
    k_scan<1><<<1, 256>>>();
    k_hist<2><<<2048, 256>>>();
    k_scan<2><<<1, 256>>>();
    k_cntmin<<<2048, 256>>>();
    k_med<<<1, 1>>>();
    k_gibbs<<<2048, 256>>>();

    k_sink<<<PBLOCKS, PTHREADS>>>();

    k_loss<<<1024, 256>>>();
    k_out<<<1, 1>>>((float*)d_out);
}